// round 8
// baseline (speedup 1.0000x reference)
#include <cuda_runtime.h>
#include <cuda_bf16.h>
#include <cstdint>
#include <math.h>

#define N_TOT    8192
#define B_HALF   4096
#define D_DIM    256
#define BLK      64
#define NBLOCKS  128         // 8192 / 64 row/col blocks
#define NTILE    8256        // 128*129/2 upper-triangle tiles
#define NTHREADS 128

#define KS_B    528          // smem row stride bytes (33*16, conflict-free ldmatrix)
#define TILE_B  (64 * KS_B)  // 33792 per 64-row tile
#define SMEM_TOTAL (3 * TILE_B)   // A + B0 + B1 = 101376 -> 2 CTAs/SM

// Scratch (__device__ globals; every value read is rewritten each run)
__device__ __nv_bfloat16 g_znb[(size_t)N_TOT * D_DIM];
__device__ float g_rowpart[NBLOCKS][NBLOCKS][BLK];   // [mt][nt], nt>=mt
__device__ float g_colpart[NBLOCKS][NBLOCKS][BLK];   // [nt][mt], mt<nt
__device__ float g_pos[N_TOT];
__device__ float g_finpart[NBLOCKS];
__device__ unsigned g_count = 0;
__device__ unsigned g_gen   = 0;

// ---------------------------------------------------------------------------
__device__ __forceinline__ uint32_t smem_u32(const void* p) {
    uint32_t a;
    asm("{ .reg .u64 t; cvta.to.shared.u64 t, %1; cvt.u32.u64 %0, t; }" : "=r"(a) : "l"(p));
    return a;
}
#define CP_ASYNC16(dst, src) \
    asm volatile("cp.async.cg.shared.global [%0], [%1], 16;" :: "r"(dst), "l"(src))
#define CP_COMMIT() asm volatile("cp.async.commit_group;" ::: "memory")
#define CP_WAIT0()  asm volatile("cp.async.wait_group 0;" ::: "memory")

#define LDSM4(r, addr) \
    asm volatile("ldmatrix.sync.aligned.m8n8.x4.shared.b16 {%0,%1,%2,%3}, [%4];" \
        : "=r"((r)[0]), "=r"((r)[1]), "=r"((r)[2]), "=r"((r)[3]) : "r"(addr))

#define MMA16816(c, a, b0, b1) \
    asm volatile("mma.sync.aligned.m16n8k16.row.col.f32.bf16.bf16.f32 " \
        "{%0,%1,%2,%3}, {%4,%5,%6,%7}, {%8,%9}, {%0,%1,%2,%3};" \
        : "+f"((c)[0]), "+f"((c)[1]), "+f"((c)[2]), "+f"((c)[3]) \
        : "r"((a)[0]), "r"((a)[1]), "r"((a)[2]), "r"((a)[3]), "r"(b0), "r"(b1))

// Sense-reversing grid barrier (grid sized to co-resident occupancy).
__device__ __forceinline__ void grid_barrier(unsigned& mygen) {
    __syncthreads();
    if (threadIdx.x == 0) {
        __threadfence();
        unsigned prev = atomicAdd(&g_count, 1u);
        if (prev == gridDim.x - 1) {
            g_count = 0;
            __threadfence();
            atomicAdd(&g_gen, 1u);
        } else {
            while (*(volatile unsigned*)&g_gen == mygen) { }
        }
        __threadfence();
    }
    __syncthreads();
    mygen++;
}

// ---------------------------------------------------------------------------
// Persistent kernel, 128 threads, 2 CTAs/SM. Phases:
// norm -> barrier -> paired-tile triangle GEMM -> barrier -> row assembly ->
// barrier -> final mean. 4 warps as 2x2; warp tile 32x32 per tile of a pair.
// ---------------------------------------------------------------------------
__global__ void __launch_bounds__(NTHREADS, 2) ntxent_mega(
        const float* __restrict__ zi, const float* __restrict__ zj,
        float* __restrict__ out) {
    extern __shared__ char smem[];
    __shared__ float red_r[2][BLK];        // [wn][row]
    __shared__ float red_c[2][2][BLK];     // [wm][tile][col]

    const int tid = threadIdx.x, lane = tid & 31, w = tid >> 5;
    const int G = gridDim.x;
    unsigned mygen = 0;

    // ================= Phase 1: normalize (warp per row) =================
    for (int row = blockIdx.x * 4 + w; row < N_TOT; row += G * 4) {
        const float4* src = (row < B_HALF)
            ? (const float4*)(zi + (size_t)row * D_DIM)
            : (const float4*)(zj + (size_t)(row - B_HALF) * D_DIM);
        float4 a = src[lane];
        float4 b = src[lane + 32];
        float s = a.x * a.x + a.y * a.y + a.z * a.z + a.w * a.w
                + b.x * b.x + b.y * b.y + b.z * b.z + b.w * b.w;
        #pragma unroll
        for (int o = 16; o > 0; o >>= 1) s += __shfl_xor_sync(0xffffffffu, s, o);
        float scale = 1.41421356237309515f / fmaxf(sqrtf(s), 1e-8f);

        __nv_bfloat16* dst = g_znb + (size_t)row * D_DIM;
        __nv_bfloat162 p0 = __floats2bfloat162_rn(a.x * scale, a.y * scale);
        __nv_bfloat162 p1 = __floats2bfloat162_rn(a.z * scale, a.w * scale);
        __nv_bfloat162 p2 = __floats2bfloat162_rn(b.x * scale, b.y * scale);
        __nv_bfloat162 p3 = __floats2bfloat162_rn(b.z * scale, b.w * scale);
        uint2 u0, u1;
        u0.x = *(uint32_t*)&p0; u0.y = *(uint32_t*)&p1;
        u1.x = *(uint32_t*)&p2; u1.y = *(uint32_t*)&p3;
        *(uint2*)(dst + lane * 4)       = u0;
        *(uint2*)(dst + 128 + lane * 4) = u1;
    }

    grid_barrier(mygen);

    // ============ Phase 2: upper-triangle GEMM, paired 64x64 tiles ============
    {
        const int wm = w >> 1, wn = w & 1;               // 2x2 warp grid
        const int warpM0 = wm * 32, warpN0 = wn * 32;    // 32x32 warp tile
        const int g = lane >> 2, tig = lane & 3;

        const uint32_t sbase = smem_u32(smem);
        const uint32_t sA = sbase;
        const uint32_t sB0 = sbase + TILE_B;
        const uint32_t sB1 = sbase + 2 * TILE_B;

        const int t0 = (int)(((long long)blockIdx.x * NTILE) / G);
        const int t1 = (int)(((long long)(blockIdx.x + 1) * NTILE) / G);

        int mt = 0, rem = t0;
        while (rem >= NBLOCKS - mt) { rem -= NBLOCKS - mt; mt++; }
        int nt = mt + rem;

        // load A(mt)
        {
            const char* gA = (const char*)(g_znb + (size_t)mt * BLK * D_DIM);
            #pragma unroll
            for (int it = 0; it < 16; it++) {
                int flat = it * NTHREADS + tid;
                int r = flat >> 5, q = flat & 31;
                CP_ASYNC16(sA + r * KS_B + q * 16, gA + r * 512 + q * 16);
            }
            CP_COMMIT();
        }

        int t = t0;
        while (t < t1) {
            int npair = t1 - t;
            if (NBLOCKS - nt < npair) npair = NBLOCKS - nt;
            if (npair > 2) npair = 2;

            // load B tiles of this step (A load from previous commit drains too)
            {
                const char* gB = (const char*)(g_znb + (size_t)nt * BLK * D_DIM);
                #pragma unroll
                for (int it = 0; it < 16; it++) {
                    int flat = it * NTHREADS + tid;
                    int r = flat >> 5, q = flat & 31;
                    CP_ASYNC16(sB0 + r * KS_B + q * 16, gB + r * 512 + q * 16);
                }
                if (npair == 2) {
                    const char* gB2 = gB + (size_t)BLK * 512;
                    #pragma unroll
                    for (int it = 0; it < 16; it++) {
                        int flat = it * NTHREADS + tid;
                        int r = flat >> 5, q = flat & 31;
                        CP_ASYNC16(sB1 + r * KS_B + q * 16, gB2 + r * 512 + q * 16);
                    }
                }
            }
            CP_COMMIT();
            CP_WAIT0();
            __syncthreads();

            // ---- k-loop: shared A frags drive both tiles of the pair ----
            float acc[2][2][4][4];
            #pragma unroll
            for (int tt = 0; tt < 2; tt++)
                #pragma unroll
                for (int mf = 0; mf < 2; mf++)
                    #pragma unroll
                    for (int nf = 0; nf < 4; nf++)
                        #pragma unroll
                        for (int e = 0; e < 4; e++) acc[tt][mf][nf][e] = 0.f;

            if (npair == 2) {
                #pragma unroll 4
                for (int kk = 0; kk < 16; kk++) {
                    const int kb = kk * 32;
                    uint32_t af[2][4], bf[2][4];
                    #pragma unroll
                    for (int mf = 0; mf < 2; mf++) {
                        uint32_t addr = sA + (warpM0 + mf * 16 + (lane & 15)) * KS_B
                                      + kb + ((lane >> 4) & 1) * 16;
                        LDSM4(af[mf], addr);
                    }
                    #pragma unroll
                    for (int p = 0; p < 2; p++) {
                        uint32_t addr = sB0 + (warpN0 + p * 16 + ((lane & 16) >> 1) + (lane & 7)) * KS_B
                                      + kb + ((lane >> 3) & 1) * 16;
                        LDSM4(bf[p], addr);
                    }
                    #pragma unroll
                    for (int mf = 0; mf < 2; mf++)
                        #pragma unroll
                        for (int nf = 0; nf < 4; nf++)
                            MMA16816(acc[0][mf][nf], af[mf], bf[nf >> 1][(nf & 1) * 2],
                                     bf[nf >> 1][(nf & 1) * 2 + 1]);
                    #pragma unroll
                    for (int p = 0; p < 2; p++) {
                        uint32_t addr = sB1 + (warpN0 + p * 16 + ((lane & 16) >> 1) + (lane & 7)) * KS_B
                                      + kb + ((lane >> 3) & 1) * 16;
                        LDSM4(bf[p], addr);
                    }
                    #pragma unroll
                    for (int mf = 0; mf < 2; mf++)
                        #pragma unroll
                        for (int nf = 0; nf < 4; nf++)
                            MMA16816(acc[1][mf][nf], af[mf], bf[nf >> 1][(nf & 1) * 2],
                                     bf[nf >> 1][(nf & 1) * 2 + 1]);
                }
            } else {
                #pragma unroll 4
                for (int kk = 0; kk < 16; kk++) {
                    const int kb = kk * 32;
                    uint32_t af[2][4], bf[2][4];
                    #pragma unroll
                    for (int mf = 0; mf < 2; mf++) {
                        uint32_t addr = sA + (warpM0 + mf * 16 + (lane & 15)) * KS_B
                                      + kb + ((lane >> 4) & 1) * 16;
                        LDSM4(af[mf], addr);
                    }
                    #pragma unroll
                    for (int p = 0; p < 2; p++) {
                        uint32_t addr = sB0 + (warpN0 + p * 16 + ((lane & 16) >> 1) + (lane & 7)) * KS_B
                                      + kb + ((lane >> 3) & 1) * 16;
                        LDSM4(bf[p], addr);
                    }
                    #pragma unroll
                    for (int mf = 0; mf < 2; mf++)
                        #pragma unroll
                        for (int nf = 0; nf < 4; nf++)
                            MMA16816(acc[0][mf][nf], af[mf], bf[nf >> 1][(nf & 1) * 2],
                                     bf[nf >> 1][(nf & 1) * 2 + 1]);
                }
            }

            // ---- epilogue: exp; rowsum over pair; colsum per tile ----
            const int m0 = mt * BLK;
            float rowsum[4];
            #pragma unroll
            for (int s = 0; s < 4; s++) rowsum[s] = 0.f;

            #pragma unroll
            for (int tt = 0; tt < 2; tt++) {
                if (tt == 1 && npair < 2) break;
                const bool is_diag = (mt == nt + tt);
                const bool is_pos  = (nt + tt == mt + 64);
                float cs[8];
                #pragma unroll
                for (int s = 0; s < 8; s++) cs[s] = 0.f;

                #pragma unroll
                for (int mf = 0; mf < 2; mf++)
                    #pragma unroll
                    for (int nf = 0; nf < 4; nf++)
                        #pragma unroll
                        for (int e = 0; e < 4; e++) {
                            float l = acc[tt][mf][nf][e];
                            float ex = __expf(l);
                            int lr = warpM0 + mf * 16 + g + (e >> 1) * 8;
                            int lc = warpN0 + nf * 8 + tig * 2 + (e & 1);
                            if (lr == lc) {
                                if (is_diag) ex = 0.f;
                                if (is_pos) {
                                    g_pos[m0 + lr] = l;
                                    g_pos[m0 + lr + B_HALF] = l;
                                }
                            }
                            rowsum[mf * 2 + (e >> 1)] += ex;
                            cs[nf * 2 + (e & 1)]      += ex;
                        }

                #pragma unroll
                for (int s = 0; s < 8; s++) {
                    cs[s] += __shfl_xor_sync(0xffffffffu, cs[s], 4);
                    cs[s] += __shfl_xor_sync(0xffffffffu, cs[s], 8);
                    cs[s] += __shfl_xor_sync(0xffffffffu, cs[s], 16);
                }
                if (g == 0) {
                    #pragma unroll
                    for (int nf = 0; nf < 4; nf++) {
                        red_c[wm][tt][warpN0 + nf * 8 + tig * 2]     = cs[nf * 2 + 0];
                        red_c[wm][tt][warpN0 + nf * 8 + tig * 2 + 1] = cs[nf * 2 + 1];
                    }
                }
            }

            #pragma unroll
            for (int s = 0; s < 4; s++) {
                rowsum[s] += __shfl_xor_sync(0xffffffffu, rowsum[s], 1);
                rowsum[s] += __shfl_xor_sync(0xffffffffu, rowsum[s], 2);
            }
            if (tig == 0) {
                red_r[wn][warpM0 + g]     = rowsum[0];
                red_r[wn][warpM0 + g + 8] = rowsum[1];
                red_r[wn][warpM0 + 16 + g]     = rowsum[2];
                red_r[wn][warpM0 + 16 + g + 8] = rowsum[3];
            }
            __syncthreads();

            if (tid < BLK) {
                g_rowpart[mt][nt][tid] = red_r[0][tid] + red_r[1][tid];
                if (npair == 2) g_rowpart[mt][nt + 1][tid] = 0.f;
                if (mt != nt)
                    g_colpart[nt][mt][tid] = red_c[0][0][tid] + red_c[1][0][tid];
                if (npair == 2)
                    g_colpart[nt + 1][mt][tid] = red_c[0][1][tid] + red_c[1][1][tid];
            }
            __syncthreads();   // slot reads done; smem reusable

            t += npair; nt += npair;
            if (nt == NBLOCKS && t < t1) {
                mt++; nt = mt;
                const char* gA = (const char*)(g_znb + (size_t)mt * BLK * D_DIM);
                #pragma unroll
                for (int it = 0; it < 16; it++) {
                    int flat = it * NTHREADS + tid;
                    int r = flat >> 5, q = flat & 31;
                    CP_ASYNC16(sA + r * KS_B + q * 16, gA + r * 512 + q * 16);
                }
                CP_COMMIT();
            }
        }
    }

    grid_barrier(mygen);

    // ============ Phase 3: per-block logsumexp assembly (128 CTAs) ============
    if (blockIdx.x < NBLOCKS) {
        const int r = blockIdx.x;
        if (tid < BLK) {
            float tot = 0.f;
            for (int nt = r; nt < NBLOCKS; nt++) tot += g_rowpart[r][nt][tid];
            for (int m = 0; m < r; m++)          tot += g_colpart[r][m][tid];
            float v = logf(tot) - g_pos[r * BLK + tid];
            #pragma unroll
            for (int o = 16; o > 0; o >>= 1) v += __shfl_xor_sync(0xffffffffu, v, o);
            if (lane == 0) red_r[0][w] = v;
        }
        __syncthreads();
        if (tid == 0) g_finpart[r] = red_r[0][0] + red_r[0][1];
    }

    grid_barrier(mygen);

    // ================= Phase 4: final mean (CTA 0) =================
    if (blockIdx.x == 0) {
        float s = (tid < NBLOCKS) ? g_finpart[tid] : 0.f;
        #pragma unroll
        for (int o = 16; o > 0; o >>= 1) s += __shfl_xor_sync(0xffffffffu, s, o);
        if (lane == 0) red_r[1][w] = s;
        __syncthreads();
        if (tid == 0)
            out[0] = ((red_r[1][0] + red_r[1][1]) + (red_r[1][2] + red_r[1][3]))
                     * (1.0f / (float)N_TOT);
    }
}

// ---------------------------------------------------------------------------
extern "C" void kernel_launch(void* const* d_in, const int* in_sizes, int n_in,
                              void* d_out, int out_size) {
    const float* zi = (const float*)d_in[0];
    const float* zj = (const float*)d_in[1];
    float* out = (float*)d_out;

    cudaFuncSetAttribute(ntxent_mega, cudaFuncAttributeMaxDynamicSharedMemorySize,
                         SMEM_TOTAL);

    int nb = 1, sms = 148;
    cudaOccupancyMaxActiveBlocksPerMultiprocessor(&nb, ntxent_mega, NTHREADS, SMEM_TOTAL);
    cudaDeviceGetAttribute(&sms, cudaDevAttrMultiProcessorCount, 0);
    int grid = nb * sms;
    if (grid < NBLOCKS) grid = NBLOCKS;   // phase 3 needs 128 CTAs

    ntxent_mega<<<grid, NTHREADS, SMEM_TOTAL>>>(zi, zj, out);
}

// round 9
// speedup vs baseline: 1.1028x; 1.1028x over previous
#include <cuda_runtime.h>
#include <cuda_bf16.h>
#include <cstdint>
#include <math.h>

#define N_TOT    8192
#define B_HALF   4096
#define D_DIM    256
#define NBLOCKS  64          // 8192 / 128 row/col blocks
#define NTILE    2080        // 64*65/2 upper-triangle tiles
#define GRID_MAIN 148
#define NTHREADS 512

#define KS_B    528          // smem row stride bytes (33*16, conflict-free ldmatrix)
#define TILE_B  (128 * KS_B) // 67584 per 128-row tile
#define SMEM_TOTAL (3 * TILE_B)   // A + 2x B = 202752

// Scratch (__device__ globals; every value read is rewritten each run)
__device__ __nv_bfloat16 g_znb[(size_t)N_TOT * D_DIM];
__device__ float g_rowpart4[NBLOCKS][NBLOCKS][4][128];  // [mt][nt][wn][row], nt>=mt
__device__ float g_colpart4[NBLOCKS][NBLOCKS][4][128];  // [nt][mt][wm][col], mt<nt
__device__ float g_pos[N_TOT];
__device__ float g_finpart[NBLOCKS];
__device__ unsigned g_count = 0;
__device__ unsigned g_gen   = 0;

// ---------------------------------------------------------------------------
__device__ __forceinline__ uint32_t smem_u32(const void* p) {
    uint32_t a;
    asm("{ .reg .u64 t; cvta.to.shared.u64 t, %1; cvt.u32.u64 %0, t; }" : "=r"(a) : "l"(p));
    return a;
}
__device__ __forceinline__ float fexp2(float x) {
    float y; asm("ex2.approx.f32 %0, %1;" : "=f"(y) : "f"(x)); return y;
}
#define CP_ASYNC16(dst, src) \
    asm volatile("cp.async.cg.shared.global [%0], [%1], 16;" :: "r"(dst), "l"(src))
#define CP_COMMIT() asm volatile("cp.async.commit_group;" ::: "memory")
#define CP_WAIT0()  asm volatile("cp.async.wait_group 0;" ::: "memory")

#define LDSM4(r, addr) \
    asm volatile("ldmatrix.sync.aligned.m8n8.x4.shared.b16 {%0,%1,%2,%3}, [%4];" \
        : "=r"((r)[0]), "=r"((r)[1]), "=r"((r)[2]), "=r"((r)[3]) : "r"(addr))

#define MMA16816(c, a, b0, b1) \
    asm volatile("mma.sync.aligned.m16n8k16.row.col.f32.bf16.bf16.f32 " \
        "{%0,%1,%2,%3}, {%4,%5,%6,%7}, {%8,%9}, {%0,%1,%2,%3};" \
        : "+f"((c)[0]), "+f"((c)[1]), "+f"((c)[2]), "+f"((c)[3]) \
        : "r"((a)[0]), "r"((a)[1]), "r"((a)[2]), "r"((a)[3]), "r"(b0), "r"(b1))

// Sense-reversing grid barrier (148 CTAs, 1/SM forced by smem -> co-resident).
__device__ __forceinline__ void grid_barrier(unsigned& mygen) {
    __syncthreads();
    if (threadIdx.x == 0) {
        __threadfence();
        unsigned prev = atomicAdd(&g_count, 1u);
        if (prev == GRID_MAIN - 1) {
            g_count = 0;
            __threadfence();
            atomicAdd(&g_gen, 1u);
        } else {
            while (*(volatile unsigned*)&g_gen == mygen) { }
        }
        __threadfence();
    }
    __syncthreads();
    mygen++;
}

// ---------------------------------------------------------------------------
// Persistent kernel, 512 threads, 1 CTA/SM. Phase 2 epilogue writes PER-WARP
// partials straight to global (no cross-warp reduce, 1 sync per tile).
// Logits kept in log2 domain: scale = sqrt(2*log2e)/||z||; exp == ex2.approx.
// ---------------------------------------------------------------------------
__global__ void __launch_bounds__(NTHREADS, 1) ntxent_mega(
        const float* __restrict__ zi, const float* __restrict__ zj,
        float* __restrict__ out) {
    extern __shared__ char smem[];
    __shared__ float red[32];

    const int tid = threadIdx.x, lane = tid & 31, w = tid >> 5;
    unsigned mygen = 0;

    // ================= Phase 1: normalize (warp per row) =================
    for (int row = blockIdx.x * 16 + w; row < N_TOT; row += GRID_MAIN * 16) {
        const float4* src = (row < B_HALF)
            ? (const float4*)(zi + (size_t)row * D_DIM)
            : (const float4*)(zj + (size_t)(row - B_HALF) * D_DIM);
        float4 a = src[lane];
        float4 b = src[lane + 32];
        float s = a.x * a.x + a.y * a.y + a.z * a.z + a.w * a.w
                + b.x * b.x + b.y * b.y + b.z * b.z + b.w * b.w;
        #pragma unroll
        for (int o = 16; o > 0; o >>= 1) s += __shfl_xor_sync(0xffffffffu, s, o);
        // scale = sqrt(2 * log2(e)) / max(||z||, eps): dot = log2(e) * sim / T
        float scale = 1.6986436f / fmaxf(sqrtf(s), 1e-8f);

        __nv_bfloat16* dst = g_znb + (size_t)row * D_DIM;
        __nv_bfloat162 p0 = __floats2bfloat162_rn(a.x * scale, a.y * scale);
        __nv_bfloat162 p1 = __floats2bfloat162_rn(a.z * scale, a.w * scale);
        __nv_bfloat162 p2 = __floats2bfloat162_rn(b.x * scale, b.y * scale);
        __nv_bfloat162 p3 = __floats2bfloat162_rn(b.z * scale, b.w * scale);
        uint2 u0, u1;
        u0.x = *(uint32_t*)&p0; u0.y = *(uint32_t*)&p1;
        u1.x = *(uint32_t*)&p2; u1.y = *(uint32_t*)&p3;
        *(uint2*)(dst + lane * 4)       = u0;
        *(uint2*)(dst + 128 + lane * 4) = u1;
    }

    grid_barrier(mygen);

    // ================= Phase 2: upper-triangle fused GEMM =================
    {
        const int wm = w >> 2, wn = w & 3;                 // 4x4 warp grid
        const int warpM0 = wm * 32, warpN0 = wn * 32;      // 32x32 warp tile
        const int g = lane >> 2, tig = lane & 3;

        const uint32_t sbase = smem_u32(smem);
        const uint32_t sA = sbase;
        const uint32_t sBb = sbase + TILE_B;

        const int t0 = (blockIdx.x * NTILE) / GRID_MAIN;
        const int t1 = ((blockIdx.x + 1) * NTILE) / GRID_MAIN;

        int mt = 0, rem = t0;
        while (rem >= NBLOCKS - mt) { rem -= NBLOCKS - mt; mt++; }
        int nt = mt + rem;

        // prologue: A(mt) and B(nt) into buf0
        {
            const char* gA = (const char*)(g_znb + (size_t)mt * 128 * D_DIM);
            const char* gB = (const char*)(g_znb + (size_t)nt * 128 * D_DIM);
            #pragma unroll
            for (int it = 0; it < 8; it++) {
                int flat = it * NTHREADS + tid;
                int r = flat >> 5, q = flat & 31;
                CP_ASYNC16(sA + r * KS_B + q * 16, gA + r * 512 + q * 16);
                CP_ASYNC16(sBb + r * KS_B + q * 16, gB + r * 512 + q * 16);
            }
        }
        CP_COMMIT();
        CP_WAIT0();
        __syncthreads();

        int cur_mt = mt;
        for (int t = t0; t < t1; t++) {
            const int buf = (t - t0) & 1;
            const bool have_next = (t + 1 < t1);
            int nmt = mt, nnt = nt + 1;
            if (nnt == NBLOCKS) { nmt = mt + 1; nnt = nmt; }

            if (have_next) {   // prefetch next tile's B into the other buffer
                const uint32_t sBn = sBb + (buf ^ 1) * TILE_B;
                const char* gB = (const char*)(g_znb + (size_t)nnt * 128 * D_DIM);
                #pragma unroll
                for (int it = 0; it < 8; it++) {
                    int flat = it * NTHREADS + tid;
                    int r = flat >> 5, q = flat & 31;
                    CP_ASYNC16(sBn + r * KS_B + q * 16, gB + r * 512 + q * 16);
                }
            }
            CP_COMMIT();

            // ---- 128x128x256 tile GEMM, 32x32 per warp ----
            const uint32_t sB = sBb + buf * TILE_B;
            float acc[2][4][4];
            #pragma unroll
            for (int mf = 0; mf < 2; mf++)
                #pragma unroll
                for (int nf = 0; nf < 4; nf++)
                    #pragma unroll
                    for (int e = 0; e < 4; e++) acc[mf][nf][e] = 0.f;

            #pragma unroll 4
            for (int kk = 0; kk < 16; kk++) {
                const int kb = kk * 32;
                uint32_t af[2][4], bf[2][4];
                #pragma unroll
                for (int mf = 0; mf < 2; mf++) {
                    uint32_t addr = sA + (warpM0 + mf * 16 + (lane & 15)) * KS_B
                                  + kb + ((lane >> 4) & 1) * 16;
                    LDSM4(af[mf], addr);
                }
                #pragma unroll
                for (int p = 0; p < 2; p++) {
                    uint32_t addr = sB + (warpN0 + p * 16 + ((lane & 16) >> 1) + (lane & 7)) * KS_B
                                  + kb + ((lane >> 3) & 1) * 16;
                    LDSM4(bf[p], addr);
                }
                #pragma unroll
                for (int mf = 0; mf < 2; mf++)
                    #pragma unroll
                    for (int nf = 0; nf < 4; nf++)
                        MMA16816(acc[mf][nf], af[mf], bf[nf >> 1][(nf & 1) * 2],
                                 bf[nf >> 1][(nf & 1) * 2 + 1]);
            }

            // ---- epilogue: ex2, per-warp row/col sums -> global slots ----
            const bool is_diag = (mt == nt);
            const bool is_pos  = (nt == mt + 32);
            const int  m0 = mt * 128;

            float rowsum[4], colsum[8];
            #pragma unroll
            for (int s = 0; s < 4; s++) rowsum[s] = 0.f;
            #pragma unroll
            for (int s = 0; s < 8; s++) colsum[s] = 0.f;

            if (is_diag | is_pos) {
                #pragma unroll
                for (int mf = 0; mf < 2; mf++)
                    #pragma unroll
                    for (int nf = 0; nf < 4; nf++)
                        #pragma unroll
                        for (int e = 0; e < 4; e++) {
                            float l = acc[mf][nf][e];
                            float ex = fexp2(l);
                            int lr = warpM0 + mf * 16 + g + (e >> 1) * 8;
                            int lc = warpN0 + nf * 8 + tig * 2 + (e & 1);
                            if (lr == lc) {
                                if (is_diag) ex = 0.f;
                                if (is_pos) {   // natural-log positive logit
                                    float ln = l * 0.69314718055994531f;
                                    g_pos[m0 + lr] = ln;
                                    g_pos[m0 + lr + B_HALF] = ln;
                                }
                            }
                            rowsum[mf * 2 + (e >> 1)] += ex;
                            colsum[nf * 2 + (e & 1)]  += ex;
                        }
            } else {
                #pragma unroll
                for (int mf = 0; mf < 2; mf++)
                    #pragma unroll
                    for (int nf = 0; nf < 4; nf++)
                        #pragma unroll
                        for (int e = 0; e < 4; e++) {
                            float ex = fexp2(acc[mf][nf][e]);
                            rowsum[mf * 2 + (e >> 1)] += ex;
                            colsum[nf * 2 + (e & 1)]  += ex;
                        }
            }

            #pragma unroll
            for (int s = 0; s < 4; s++) {
                rowsum[s] += __shfl_xor_sync(0xffffffffu, rowsum[s], 1);
                rowsum[s] += __shfl_xor_sync(0xffffffffu, rowsum[s], 2);
            }
            #pragma unroll
            for (int s = 0; s < 8; s++) {
                colsum[s] += __shfl_xor_sync(0xffffffffu, colsum[s], 4);
                colsum[s] += __shfl_xor_sync(0xffffffffu, colsum[s], 8);
                colsum[s] += __shfl_xor_sync(0xffffffffu, colsum[s], 16);
            }
            if (tig == 0) {   // 8 lanes: rows warpM0 + mf*16 + g + h*8
                float* rp = &g_rowpart4[mt][nt][wn][0];
                rp[warpM0 + g]          = rowsum[0];
                rp[warpM0 + g + 8]      = rowsum[1];
                rp[warpM0 + 16 + g]     = rowsum[2];
                rp[warpM0 + 16 + g + 8] = rowsum[3];
            }
            if (g == 0 && !is_diag) {   // 4 lanes: cols warpN0 + nf*8 + tig*2 + b
                float* cp = &g_colpart4[nt][mt][wm][0];
                #pragma unroll
                for (int nf = 0; nf < 4; nf++) {
                    cp[warpN0 + nf * 8 + tig * 2]     = colsum[nf * 2 + 0];
                    cp[warpN0 + nf * 8 + tig * 2 + 1] = colsum[nf * 2 + 1];
                }
            }

            CP_WAIT0();
            __syncthreads();   // B(next) visible to all; buf reusable

            if (have_next && nmt != cur_mt) {   // A reload on row change
                const char* gA = (const char*)(g_znb + (size_t)nmt * 128 * D_DIM);
                #pragma unroll
                for (int it = 0; it < 8; it++) {
                    int flat = it * NTHREADS + tid;
                    int r = flat >> 5, q = flat & 31;
                    CP_ASYNC16(sA + r * KS_B + q * 16, gA + r * 512 + q * 16);
                }
                CP_COMMIT();
                CP_WAIT0();
                __syncthreads();
                cur_mt = nmt;
            }
            mt = nmt; nt = nnt;
        }
    }

    grid_barrier(mygen);

    // ============ Phase 3: per-block logsumexp assembly (64 CTAs) ============
    if (blockIdx.x < NBLOCKS && tid < 128) {
        const int r = blockIdx.x;
        float tot = 0.f;
        for (int nt = r; nt < NBLOCKS; nt++) {
            const float* rp = &g_rowpart4[r][nt][0][0];
            tot += (rp[tid] + rp[128 + tid]) + (rp[256 + tid] + rp[384 + tid]);
        }
        for (int m = 0; m < r; m++) {
            const float* cp = &g_colpart4[r][m][0][0];
            tot += (cp[tid] + cp[128 + tid]) + (cp[256 + tid] + cp[384 + tid]);
        }
        float v = logf(tot) - g_pos[r * 128 + tid];
        #pragma unroll
        for (int o = 16; o > 0; o >>= 1) v += __shfl_xor_sync(0xffffffffu, v, o);
        if (lane == 0) red[w] = v;
        __syncwarp();
    }
    __syncthreads();
    if (blockIdx.x < NBLOCKS && tid == 0) {
        g_finpart[blockIdx.x] = (red[0] + red[1]) + (red[2] + red[3]);
    }

    grid_barrier(mygen);

    // ================= Phase 4: final mean (CTA 0) =================
    if (blockIdx.x == 0 && tid < 64) {
        float s = g_finpart[tid];
        #pragma unroll
        for (int o = 16; o > 0; o >>= 1) s += __shfl_xor_sync(0xffffffffu, s, o);
        if (lane == 0) red[8 + (tid >> 5)] = s;
        __syncwarp();
        if (tid == 0) out[0] = (red[8] + red[9]) * (1.0f / (float)N_TOT);
    }
}

// ---------------------------------------------------------------------------
extern "C" void kernel_launch(void* const* d_in, const int* in_sizes, int n_in,
                              void* d_out, int out_size) {
    const float* zi = (const float*)d_in[0];
    const float* zj = (const float*)d_in[1];
    float* out = (float*)d_out;

    cudaFuncSetAttribute(ntxent_mega, cudaFuncAttributeMaxDynamicSharedMemorySize,
                         SMEM_TOTAL);

    ntxent_mega<<<GRID_MAIN, NTHREADS, SMEM_TOTAL>>>(zi, zj, out);
}

// round 10
// speedup vs baseline: 1.1659x; 1.0572x over previous
#include <cuda_runtime.h>
#include <cuda_bf16.h>
#include <cstdint>
#include <math.h>

#define N_TOT    8192
#define B_HALF   4096
#define D_DIM    256
#define NBLOCKS  64          // 8192 / 128 row/col blocks
#define NTILE    2080        // 64*65/2 upper-triangle tiles
#define GRID_MAIN 148
#define NTHREADS 256

#define KS_B    528          // smem row stride bytes (33*16, conflict-free ldmatrix)
#define TILE_B  (128 * KS_B) // 67584 per 128-row tile
#define SMEM_TOTAL (3 * TILE_B)   // A + 2x B = 202752

// Scratch (__device__ globals; every value read is rewritten each run)
__device__ __nv_bfloat16 g_znb[(size_t)N_TOT * D_DIM];
__device__ float g_rowpart4[NBLOCKS][NBLOCKS][4][128];  // [mt][nt][wn][row], nt>=mt
__device__ float g_colpart2[NBLOCKS][NBLOCKS][2][128];  // [nt][mt][wm][col], mt<nt
__device__ float g_pos[N_TOT];
__device__ float g_finpart[NBLOCKS];
__device__ unsigned g_count = 0;
__device__ unsigned g_gen   = 0;

// ---------------------------------------------------------------------------
__device__ __forceinline__ uint32_t smem_u32(const void* p) {
    uint32_t a;
    asm("{ .reg .u64 t; cvta.to.shared.u64 t, %1; cvt.u32.u64 %0, t; }" : "=r"(a) : "l"(p));
    return a;
}
__device__ __forceinline__ float fexp2(float x) {
    float y; asm("ex2.approx.f32 %0, %1;" : "=f"(y) : "f"(x)); return y;
}
#define CP_ASYNC16(dst, src) \
    asm volatile("cp.async.cg.shared.global [%0], [%1], 16;" :: "r"(dst), "l"(src))
#define CP_COMMIT() asm volatile("cp.async.commit_group;" ::: "memory")
#define CP_WAIT0()  asm volatile("cp.async.wait_group 0;" ::: "memory")

#define LDSM4(r, addr) \
    asm volatile("ldmatrix.sync.aligned.m8n8.x4.shared.b16 {%0,%1,%2,%3}, [%4];" \
        : "=r"((r)[0]), "=r"((r)[1]), "=r"((r)[2]), "=r"((r)[3]) : "r"(addr))

#define MMA16816(c, a, b0, b1) \
    asm volatile("mma.sync.aligned.m16n8k16.row.col.f32.bf16.bf16.f32 " \
        "{%0,%1,%2,%3}, {%4,%5,%6,%7}, {%8,%9}, {%0,%1,%2,%3};" \
        : "+f"((c)[0]), "+f"((c)[1]), "+f"((c)[2]), "+f"((c)[3]) \
        : "r"((a)[0]), "r"((a)[1]), "r"((a)[2]), "r"((a)[3]), "r"(b0), "r"(b1))

// Sense-reversing grid barrier (148 CTAs, 1/SM forced by smem -> co-resident).
__device__ __forceinline__ void grid_barrier(unsigned& mygen) {
    __syncthreads();
    if (threadIdx.x == 0) {
        __threadfence();
        unsigned prev = atomicAdd(&g_count, 1u);
        if (prev == GRID_MAIN - 1) {
            g_count = 0;
            __threadfence();
            atomicAdd(&g_gen, 1u);
        } else {
            while (*(volatile unsigned*)&g_gen == mygen) { }
        }
        __threadfence();
    }
    __syncthreads();
    mygen++;
}

// ---------------------------------------------------------------------------
// Persistent kernel, 256 threads (8 warps, 2x4, 64x32 warp tiles), 1 CTA/SM.
// k-loop is register double-buffered: LDSM for step k+1 issue BEFORE the MMAs
// of step k, so ldmatrix latency hides under tensor work.
// Logits in log2 domain (ex2.approx); per-warp partial sums straight to global.
// ---------------------------------------------------------------------------
__global__ void __launch_bounds__(NTHREADS, 1) ntxent_mega(
        const float* __restrict__ zi, const float* __restrict__ zj,
        float* __restrict__ out) {
    extern __shared__ char smem[];
    __shared__ float red[32];

    const int tid = threadIdx.x, lane = tid & 31, w = tid >> 5;
    unsigned mygen = 0;

    // ================= Phase 1: normalize (warp per row) =================
    for (int row = blockIdx.x * 8 + w; row < N_TOT; row += GRID_MAIN * 8) {
        const float4* src = (row < B_HALF)
            ? (const float4*)(zi + (size_t)row * D_DIM)
            : (const float4*)(zj + (size_t)(row - B_HALF) * D_DIM);
        float4 a = src[lane];
        float4 b = src[lane + 32];
        float s = a.x * a.x + a.y * a.y + a.z * a.z + a.w * a.w
                + b.x * b.x + b.y * b.y + b.z * b.z + b.w * b.w;
        #pragma unroll
        for (int o = 16; o > 0; o >>= 1) s += __shfl_xor_sync(0xffffffffu, s, o);
        // scale = sqrt(2 * log2(e)) / max(||z||, eps): dot = log2(e) * sim / T
        float scale = 1.6986436f / fmaxf(sqrtf(s), 1e-8f);

        __nv_bfloat16* dst = g_znb + (size_t)row * D_DIM;
        __nv_bfloat162 p0 = __floats2bfloat162_rn(a.x * scale, a.y * scale);
        __nv_bfloat162 p1 = __floats2bfloat162_rn(a.z * scale, a.w * scale);
        __nv_bfloat162 p2 = __floats2bfloat162_rn(b.x * scale, b.y * scale);
        __nv_bfloat162 p3 = __floats2bfloat162_rn(b.z * scale, b.w * scale);
        uint2 u0, u1;
        u0.x = *(uint32_t*)&p0; u0.y = *(uint32_t*)&p1;
        u1.x = *(uint32_t*)&p2; u1.y = *(uint32_t*)&p3;
        *(uint2*)(dst + lane * 4)       = u0;
        *(uint2*)(dst + 128 + lane * 4) = u1;
    }

    grid_barrier(mygen);

    // ================= Phase 2: upper-triangle fused GEMM =================
    {
        const int wm = w >> 2, wn = w & 3;                 // 2x4 warp grid
        const int warpM0 = wm * 64, warpN0 = wn * 32;      // 64x32 warp tile
        const int g = lane >> 2, tig = lane & 3;

        const uint32_t sbase = smem_u32(smem);
        const uint32_t sA = sbase;
        const uint32_t sBb = sbase + TILE_B;

        // per-warp base addresses for fragment loads (k offset added per step)
        const uint32_t aAddr0 = sA + (warpM0 + (lane & 15)) * KS_B + ((lane >> 4) & 1) * 16;
        const uint32_t bOff0  = (warpN0 + ((lane & 16) >> 1) + (lane & 7)) * KS_B
                              + ((lane >> 3) & 1) * 16;

        const int t0 = (blockIdx.x * NTILE) / GRID_MAIN;
        const int t1 = ((blockIdx.x + 1) * NTILE) / GRID_MAIN;

        int mt = 0, rem = t0;
        while (rem >= NBLOCKS - mt) { rem -= NBLOCKS - mt; mt++; }
        int nt = mt + rem;

        // prologue: A(mt) and B(nt) into buf0
        {
            const char* gA = (const char*)(g_znb + (size_t)mt * 128 * D_DIM);
            const char* gB = (const char*)(g_znb + (size_t)nt * 128 * D_DIM);
            #pragma unroll
            for (int it = 0; it < 16; it++) {
                int flat = it * NTHREADS + tid;
                int r = flat >> 5, q = flat & 31;
                CP_ASYNC16(sA + r * KS_B + q * 16, gA + r * 512 + q * 16);
                CP_ASYNC16(sBb + r * KS_B + q * 16, gB + r * 512 + q * 16);
            }
        }
        CP_COMMIT();
        CP_WAIT0();
        __syncthreads();

        int cur_mt = mt;
        for (int t = t0; t < t1; t++) {
            const int buf = (t - t0) & 1;
            const bool have_next = (t + 1 < t1);
            int nmt = mt, nnt = nt + 1;
            if (nnt == NBLOCKS) { nmt = mt + 1; nnt = nmt; }

            if (have_next) {   // prefetch next tile's B into the other buffer
                const uint32_t sBn = sBb + (buf ^ 1) * TILE_B;
                const char* gB = (const char*)(g_znb + (size_t)nnt * 128 * D_DIM);
                #pragma unroll
                for (int it = 0; it < 16; it++) {
                    int flat = it * NTHREADS + tid;
                    int r = flat >> 5, q = flat & 31;
                    CP_ASYNC16(sBn + r * KS_B + q * 16, gB + r * 512 + q * 16);
                }
            }
            CP_COMMIT();

            // ---- 128x128x256 tile GEMM, 64x32 per warp, reg-pipelined ----
            const uint32_t sB = sBb + buf * TILE_B;
            const uint32_t bAddr0 = sB + bOff0;

            float acc[4][4][4];
            #pragma unroll
            for (int mf = 0; mf < 4; mf++)
                #pragma unroll
                for (int nf = 0; nf < 4; nf++)
                    #pragma unroll
                    for (int e = 0; e < 4; e++) acc[mf][nf][e] = 0.f;

            uint32_t af[2][4][4], bf[2][2][4];
            // preload k-step 0 into set 0
            #pragma unroll
            for (int mf = 0; mf < 4; mf++) LDSM4(af[0][mf], aAddr0 + mf * (16 * KS_B));
            #pragma unroll
            for (int p = 0; p < 2; p++)    LDSM4(bf[0][p],  bAddr0 + p * (16 * KS_B));

            #pragma unroll
            for (int kk = 0; kk < 16; kk++) {
                const int cur = kk & 1, nxt = cur ^ 1;
                if (kk < 15) {   // issue next step's LDSMs first: latency hides under MMAs
                    const int kb = (kk + 1) * 32;
                    #pragma unroll
                    for (int mf = 0; mf < 4; mf++)
                        LDSM4(af[nxt][mf], aAddr0 + mf * (16 * KS_B) + kb);
                    #pragma unroll
                    for (int p = 0; p < 2; p++)
                        LDSM4(bf[nxt][p],  bAddr0 + p * (16 * KS_B) + kb);
                }
                #pragma unroll
                for (int mf = 0; mf < 4; mf++)
                    #pragma unroll
                    for (int nf = 0; nf < 4; nf++)
                        MMA16816(acc[mf][nf], af[cur][mf], bf[cur][nf >> 1][(nf & 1) * 2],
                                 bf[cur][nf >> 1][(nf & 1) * 2 + 1]);
            }

            // ---- epilogue: ex2, per-warp row/col sums -> global slots ----
            const bool is_diag = (mt == nt);
            const bool is_pos  = (nt == mt + 32);
            const int  m0 = mt * 128;

            float rowsum[8], colsum[8];
            #pragma unroll
            for (int s = 0; s < 8; s++) { rowsum[s] = 0.f; colsum[s] = 0.f; }

            if (is_diag | is_pos) {
                #pragma unroll
                for (int mf = 0; mf < 4; mf++)
                    #pragma unroll
                    for (int nf = 0; nf < 4; nf++)
                        #pragma unroll
                        for (int e = 0; e < 4; e++) {
                            float l = acc[mf][nf][e];
                            float ex = fexp2(l);
                            int lr = warpM0 + mf * 16 + g + (e >> 1) * 8;
                            int lc = warpN0 + nf * 8 + tig * 2 + (e & 1);
                            if (lr == lc) {
                                if (is_diag) ex = 0.f;
                                if (is_pos) {   // natural-log positive logit
                                    float ln = l * 0.69314718055994531f;
                                    g_pos[m0 + lr] = ln;
                                    g_pos[m0 + lr + B_HALF] = ln;
                                }
                            }
                            rowsum[mf * 2 + (e >> 1)] += ex;
                            colsum[nf * 2 + (e & 1)]  += ex;
                        }
            } else {
                #pragma unroll
                for (int mf = 0; mf < 4; mf++)
                    #pragma unroll
                    for (int nf = 0; nf < 4; nf++)
                        #pragma unroll
                        for (int e = 0; e < 4; e++) {
                            float ex = fexp2(acc[mf][nf][e]);
                            rowsum[mf * 2 + (e >> 1)] += ex;
                            colsum[nf * 2 + (e & 1)]  += ex;
                        }
            }

            #pragma unroll
            for (int s = 0; s < 8; s++) {
                rowsum[s] += __shfl_xor_sync(0xffffffffu, rowsum[s], 1);
                rowsum[s] += __shfl_xor_sync(0xffffffffu, rowsum[s], 2);
            }
            #pragma unroll
            for (int s = 0; s < 8; s++) {
                colsum[s] += __shfl_xor_sync(0xffffffffu, colsum[s], 4);
                colsum[s] += __shfl_xor_sync(0xffffffffu, colsum[s], 8);
                colsum[s] += __shfl_xor_sync(0xffffffffu, colsum[s], 16);
            }
            if (tig == 0) {   // 8 lanes: rows warpM0 + mf*16 + g + h*8
                float* rp = &g_rowpart4[mt][nt][wn][0];
                #pragma unroll
                for (int mf = 0; mf < 4; mf++) {
                    rp[warpM0 + mf * 16 + g]     = rowsum[mf * 2 + 0];
                    rp[warpM0 + mf * 16 + g + 8] = rowsum[mf * 2 + 1];
                }
            }
            if (g == 0 && !is_diag) {   // 4 lanes: cols warpN0 + nf*8 + tig*2 + b
                float* cp = &g_colpart2[nt][mt][wm][0];
                #pragma unroll
                for (int nf = 0; nf < 4; nf++) {
                    cp[warpN0 + nf * 8 + tig * 2]     = colsum[nf * 2 + 0];
                    cp[warpN0 + nf * 8 + tig * 2 + 1] = colsum[nf * 2 + 1];
                }
            }

            CP_WAIT0();
            __syncthreads();   // B(next) visible; buf reusable

            if (have_next && nmt != cur_mt) {   // A reload on row change
                const char* gA = (const char*)(g_znb + (size_t)nmt * 128 * D_DIM);
                #pragma unroll
                for (int it = 0; it < 16; it++) {
                    int flat = it * NTHREADS + tid;
                    int r = flat >> 5, q = flat & 31;
                    CP_ASYNC16(sA + r * KS_B + q * 16, gA + r * 512 + q * 16);
                }
                CP_COMMIT();
                CP_WAIT0();
                __syncthreads();
                cur_mt = nmt;
            }
            mt = nmt; nt = nnt;
        }
    }

    grid_barrier(mygen);

    // ============ Phase 3: per-block logsumexp assembly (64 CTAs) ============
    if (blockIdx.x < NBLOCKS && tid < 128) {
        const int r = blockIdx.x;
        float tot = 0.f;
        for (int nt = r; nt < NBLOCKS; nt++) {
            const float* rp = &g_rowpart4[r][nt][0][0];
            tot += (rp[tid] + rp[128 + tid]) + (rp[256 + tid] + rp[384 + tid]);
        }
        for (int m = 0; m < r; m++) {
            const float* cp = &g_colpart2[r][m][0][0];
            tot += cp[tid] + cp[128 + tid];
        }
        float v = logf(tot) - g_pos[r * 128 + tid];
        #pragma unroll
        for (int o = 16; o > 0; o >>= 1) v += __shfl_xor_sync(0xffffffffu, v, o);
        if (lane == 0) red[w] = v;
        __syncwarp();
    }
    __syncthreads();
    if (blockIdx.x < NBLOCKS && tid == 0) {
        g_finpart[blockIdx.x] = (red[0] + red[1]) + (red[2] + red[3]);
    }

    grid_barrier(mygen);

    // ================= Phase 4: final mean (CTA 0) =================
    if (blockIdx.x == 0 && tid < 64) {
        float s = g_finpart[tid];
        #pragma unroll
        for (int o = 16; o > 0; o >>= 1) s += __shfl_xor_sync(0xffffffffu, s, o);
        if (lane == 0) red[8 + (tid >> 5)] = s;
        __syncwarp();
        if (tid == 0) out[0] = (red[8] + red[9]) * (1.0f / (float)N_TOT);
    }
}

// ---------------------------------------------------------------------------
extern "C" void kernel_launch(void* const* d_in, const int* in_sizes, int n_in,
                              void* d_out, int out_size) {
    const float* zi = (const float*)d_in[0];
    const float* zj = (const float*)d_in[1];
    float* out = (float*)d_out;

    cudaFuncSetAttribute(ntxent_mega, cudaFuncAttributeMaxDynamicSharedMemorySize,
                         SMEM_TOTAL);

    ntxent_mega<<<GRID_MAIN, NTHREADS, SMEM_TOTAL>>>(zi, zj, out);
}